// round 16
// baseline (speedup 1.0000x reference)
#include <cuda_runtime.h>
#include <cstdint>

// Problem dims
#define TT 2048
#define BB 64
#define DD 128
#define HH 256
#define CC 5

// 134 MB scratch for x_proj (allowed: __device__ global, no runtime alloc)
__device__ float g_xproj[TT * BB * HH];

// ---------- helpers ----------
__device__ __forceinline__ float2 up2(unsigned long long v) {
    float2 r;
    asm("mov.b64 {%0,%1}, %2;" : "=f"(r.x), "=f"(r.y) : "l"(v));
    return r;
}
#define FMA2(d, a, b) asm("fma.rn.f32x2 %0, %1, %2, %0;" : "+l"(d) : "l"(a), "l"(b))

__device__ __forceinline__ uint32_t smem_u32(const void* p) {
    uint32_t a;
    asm("{ .reg .u64 t; cvta.to.shared.u64 t, %1; cvt.u32.u64 %0, t; }" : "=r"(a) : "l"(p));
    return a;
}

// fast tanh: 1 - 2/(e^{2x}+1), err ~5e-7, clamped (correctness-proven)
__device__ __forceinline__ float tanh_fast(float x) {
    float xc = fminf(fmaxf(x, -15.0f), 15.0f);
    float e  = __expf(2.0f * xc);
    return fmaf(-2.0f, __frcp_rn(e + 1.0f), 1.0f);
}

#define MBAR_WAIT(addr, parity)                                              \
    asm volatile(                                                            \
        "{\n\t.reg .pred P;\n"                                               \
        "W%=:\n\t"                                                           \
        "mbarrier.try_wait.parity.acquire.cta.shared::cta.b64 P, [%0], %1, 0x989680;\n\t" \
        "@!P bra W%=;\n\t}"                                                  \
        :: "r"(addr), "r"(parity) : "memory")

// =====================================================================
// Kernel 1: x_proj — unchanged from R12 (passed; ~280us).
// =====================================================================
#define WPAD 130

__global__ __launch_bounds__(256) void xproj_kernel(
    const float* __restrict__ x, const float* __restrict__ Wih,
    const float* __restrict__ bih, const float* __restrict__ bhh)
{
    extern __shared__ float sm[];
    float* Wsm = sm;                    // [256][WPAD]
    float* Xsm = sm + 256 * WPAD;       // [2][64][128]
    const int t0 = blockIdx.x * 2, tid = threadIdx.x;

    for (int i = tid; i < 256 * 128; i += 256) {
        int j = i >> 7, k = i & 127;
        Wsm[j * WPAD + k] = Wih[i];
    }
    const float* xt = x + (size_t)t0 * BB * DD;
    for (int i = tid; i < 2 * BB * DD; i += 256) Xsm[i] = xt[i];
    __syncthreads();

    const int bx = tid >> 5;
    const int jx = tid & 31;

    float bsum[8];
#pragma unroll
    for (int c = 0; c < 8; c++) {
        int j = jx + 32 * c;
        bsum[c] = bih[j] + bhh[j];
    }

    const unsigned long long* Wu = (const unsigned long long*)Wsm;  // row stride 65

    for (int tt = 0; tt < 2; tt++) {
        unsigned long long acc[8][8];
#pragma unroll
        for (int b = 0; b < 8; b++)
#pragma unroll
            for (int c = 0; c < 8; c++) acc[b][c] = 0ULL;

        const unsigned long long* Xu =
            (const unsigned long long*)(Xsm + tt * BB * DD);  // row stride 64

#pragma unroll 2
        for (int kp = 0; kp < 64; kp++) {
            unsigned long long w[8];
#pragma unroll
            for (int c = 0; c < 8; c++) w[c] = Wu[(jx + 32 * c) * 65 + kp];
#pragma unroll
            for (int b = 0; b < 8; b++) {
                unsigned long long a = Xu[(bx * 8 + b) * 64 + kp];
#pragma unroll
                for (int c = 0; c < 8; c++) FMA2(acc[b][c], w[c], a);
            }
        }

        float* op = g_xproj + (size_t)(t0 + tt) * BB * HH;
#pragma unroll
        for (int b = 0; b < 8; b++) {
#pragma unroll
            for (int c = 0; c < 8; c++) {
                float2 f = up2(acc[b][c]);
                op[(bx * 8 + b) * HH + jx + 32 * c] = f.x + f.y + bsum[c];
            }
        }
    }
}

// =====================================================================
// Kernel 2: recurrence + head. 64 clusters x 2 CTAs, 768 threads/CTA.
// 6 threads per output row (k coverage audited, sums to 256):
//   Reducers (tid<256, 2/row): own k [rank*128+32*rsub, +32)   — 16 FMA2
//   Remote (tid>=256, 4/row):  own k [rank*128+64+16*mg, +16)  —  8 FMA2 pre-wait
//                              peer k [(rank^1)*128+32*mg,+32) — 16 FMA2 post-wait
// Per step: stage A (reducer matvec + remote own-k, both hidden under the
// DSMEM fabric window) | remote: mbar wait -> peer matvec -> STS | syncA |
// tail (warps 0-3): part+psum2+4*psum+xp -> tanh -> STS own + st.async push
// -> arm (after syncA => after all phase-(t-1) waits: R12-validated rule)
// | syncB (own-half h visible for next stage A).
// =====================================================================
__global__ void __launch_bounds__(768, 1) __cluster_dims__(2, 1, 1)
rnn_kernel(const float* __restrict__ Whh, const float* __restrict__ Wfc,
           const float* __restrict__ bfc, float* __restrict__ out)
{
    __shared__ __align__(16) float hbuf[2][HH];
    __shared__ float psum[512];    // remote partials (own16 + peer32 k each)
    __shared__ float psum2[128];   // reducer sub1 partials
    __shared__ __align__(8) unsigned long long mbar_store;
    __shared__ float logits_sm[8];

    const int tid  = threadIdx.x;
    const int rank = blockIdx.x & 1;
    const int b    = blockIdx.x >> 1;
    const bool red = (tid < 256);

    const int rrow = tid & 127;     // reducers: row
    const int rsub = (tid >> 7) & 1;
    const int idx  = tid - 256;     // remote: 0..511
    const int mrow = idx & 127;
    const int mg   = idx >> 7;      // 0..3

    // --- W_hh slices into registers ---
    unsigned long long W2[24];
    if (red) {
        // row (rank*128+rrow), own k [rank*128 + 32*rsub, +32): 32 floats
        const ulonglong2* pw = (const ulonglong2*)(
            Whh + (size_t)(rank * 128 + rrow) * HH + rank * 128 + 32 * rsub);
#pragma unroll
        for (int m = 0; m < 8; m++) {
            ulonglong2 v = pw[m];
            W2[2 * m]     = v.x;
            W2[2 * m + 1] = v.y;
        }
#pragma unroll
        for (int m = 16; m < 24; m++) W2[m] = 0ULL;
    } else {
        const float* wrow = Whh + (size_t)(rank * 128 + mrow) * HH;
        // own k [rank*128 + 64 + 16*mg, +16): 16 floats -> W2[0..7]
        const ulonglong2* pa =
            (const ulonglong2*)(wrow + rank * 128 + 64 + 16 * mg);
#pragma unroll
        for (int m = 0; m < 4; m++) {
            ulonglong2 v = pa[m];
            W2[2 * m]     = v.x;
            W2[2 * m + 1] = v.y;
        }
        // peer k [(rank^1)*128 + 32*mg, +32): 32 floats -> W2[8..23]
        const ulonglong2* pb =
            (const ulonglong2*)(wrow + (rank ^ 1) * 128 + 32 * mg);
#pragma unroll
        for (int m = 0; m < 8; m++) {
            ulonglong2 v = pb[m];
            W2[8 + 2 * m] = v.x;
            W2[9 + 2 * m] = v.y;
        }
    }

    // h0 = 0
    for (int i = tid; i < 2 * HH; i += 768) ((float*)hbuf)[i] = 0.0f;

    const uint32_t mbar_local = smem_u32(&mbar_store);
    if (tid == 0) {
        asm volatile("mbarrier.init.shared.b64 [%0], %1;"
                     :: "r"(mbar_local), "r"(1) : "memory");
    }
    __syncthreads();
    asm volatile("barrier.cluster.arrive.aligned;" ::: "memory");
    asm volatile("barrier.cluster.wait.aligned;" ::: "memory");

    const uint32_t peer = rank ^ 1;
    uint32_t mbar_peer, hbuf_peer;
    asm("mapa.shared::cluster.u32 %0, %1, %2;" : "=r"(mbar_peer)
        : "r"(mbar_local), "r"(peer));
    asm("mapa.shared::cluster.u32 %0, %1, %2;" : "=r"(hbuf_peer)
        : "r"(smem_u32(&hbuf[0][0])), "r"(peer));

    const float* xrow = g_xproj + (size_t)b * HH + rank * 128 + tid;  // tid<128
    const int xstride = BB * HH;

    int p = 0;
    float xp_cur = 0.0f, xp_next = 0.0f;
    if (tid < 128) xp_cur = xrow[0];

    const int kown = rank * 128 + 32 * rsub;           // reducers
    const int kro  = rank * 128 + 64 + 16 * mg;        // remote, own pre-wait
    const int krp  = (rank ^ 1) * 128 + 32 * mg;       // remote, peer post-wait

#pragma unroll 1
    for (int t = 0; t < TT; t++) {
        float part = 0.0f;
        if (red) {
            // ---------- REDUCERS: stage A (hidden under fabric) ----------
            if (tid < 128 && t + 1 < TT) xp_next = xrow[(size_t)(t + 1) * xstride];

            const ulonglong2* hu = (const ulonglong2*)(&hbuf[p][kown]);
            unsigned long long a0 = 0ULL, a1 = 0ULL, a2 = 0ULL, a3 = 0ULL;
#pragma unroll
            for (int mm = 0; mm < 4; mm++) {
                ulonglong2 h0 = hu[2 * mm];
                ulonglong2 h1 = hu[2 * mm + 1];
                FMA2(a0, W2[4 * mm],     h0.x);
                FMA2(a1, W2[4 * mm + 1], h0.y);
                FMA2(a2, W2[4 * mm + 2], h1.x);
                FMA2(a3, W2[4 * mm + 3], h1.y);
            }
            float2 f0 = up2(a0), f1 = up2(a1), f2 = up2(a2), f3 = up2(a3);
            part = ((f0.x + f0.y) + (f1.x + f1.y)) +
                   ((f2.x + f2.y) + (f3.x + f3.y));
            if (tid >= 128) psum2[rrow] = part;
        } else {
            // ---------- REMOTE: own-k pre-wait (hidden), peer-k post-wait ----------
            unsigned long long a0 = 0ULL, a1 = 0ULL, a2 = 0ULL, a3 = 0ULL;
            {   // own 16 k (slot p own-half visible via syncB of t-1)
                const ulonglong2* hu = (const ulonglong2*)(&hbuf[p][kro]);
#pragma unroll
                for (int mm = 0; mm < 2; mm++) {
                    ulonglong2 h0 = hu[2 * mm];
                    ulonglong2 h1 = hu[2 * mm + 1];
                    FMA2(a0, W2[4 * mm],     h0.x);
                    FMA2(a1, W2[4 * mm + 1], h0.y);
                    FMA2(a2, W2[4 * mm + 2], h1.x);
                    FMA2(a3, W2[4 * mm + 3], h1.y);
                }
            }
            if (t > 0) MBAR_WAIT(mbar_local, (t - 1) & 1);
            {   // peer 32 k
                const ulonglong2* hu = (const ulonglong2*)(&hbuf[p][krp]);
#pragma unroll
                for (int mm = 0; mm < 4; mm++) {
                    ulonglong2 h0 = hu[2 * mm];
                    ulonglong2 h1 = hu[2 * mm + 1];
                    FMA2(a0, W2[8 + 4 * mm],  h0.x);
                    FMA2(a1, W2[9 + 4 * mm],  h0.y);
                    FMA2(a2, W2[10 + 4 * mm], h1.x);
                    FMA2(a3, W2[11 + 4 * mm], h1.y);
                }
            }
            float2 f0 = up2(a0), f1 = up2(a1), f2 = up2(a2), f3 = up2(a3);
            psum[idx] = ((f0.x + f0.y) + (f1.x + f1.y)) +
                        ((f2.x + f2.y) + (f3.x + f3.y));
        }

        __syncthreads();  // syncA: all partials visible; after all ph-(t-1) waits

        if (tid < 128) {
            // ---------- tail: combine + tanh + publish ----------
            float s = part + psum2[tid] + xp_cur
                    + (psum[tid] + psum[tid + 128])
                    + (psum[tid + 256] + psum[tid + 384]);
            float hn = tanh_fast(s);
            int pn = p ^ 1;
            hbuf[pn][rank * 128 + tid] = hn;  // own copy
            if ((rank == 1) || (t + 1 < TT)) {
                uint32_t dst = hbuf_peer +
                    (uint32_t)((pn * HH + rank * 128 + tid) * 4);
                asm volatile(
                    "st.async.shared::cluster.mbarrier::complete_tx::bytes.b32 [%0], %1, [%2];"
                    :: "r"(dst), "r"(__float_as_uint(hn)), "r"(mbar_peer) : "memory");
            }
        }
        // arm phase t (after syncA => after all phase-(t-1) waits)
        if (tid == 0 && ((rank == 0) || (t + 1 < TT))) {
            asm volatile("mbarrier.arrive.expect_tx.shared.b64 _, [%0], %1;"
                         :: "r"(mbar_local), "r"(512) : "memory");
        }
        __syncthreads();  // syncB: own-half h visible for next stage A

        p ^= 1;
        xp_cur = xp_next;
    }

    // --- head: rank 0 waits for rank1's final push, logits + log_softmax ---
    if (rank == 0) {
        MBAR_WAIT(mbar_local, 1);  // phase TT-1 (parity 1): rank1's last half
        const int w = tid >> 5, l = tid & 31;
        if (w < CC) {
            float sacc = 0.0f;
#pragma unroll
            for (int q = 0; q < 8; q++)
                sacc += hbuf[0][l + 32 * q] * Wfc[w * HH + l + 32 * q];
#pragma unroll
            for (int off = 16; off > 0; off >>= 1)
                sacc += __shfl_xor_sync(0xffffffffu, sacc, off);
            if (l == 0) logits_sm[w] = sacc + bfc[w];
        }
        __syncthreads();
        if (tid == 0) {
            float m = logits_sm[0];
#pragma unroll
            for (int c = 1; c < CC; c++) m = fmaxf(m, logits_sm[c]);
            float se = 0.0f;
#pragma unroll
            for (int c = 0; c < CC; c++) se += expf(logits_sm[c] - m);
            float lse = logf(se);
#pragma unroll
            for (int c = 0; c < CC; c++)
                out[b * CC + c] = logits_sm[c] - m - lse;
        }
    }
}

// =====================================================================
// launch
// =====================================================================
extern "C" void kernel_launch(void* const* d_in, const int* in_sizes, int n_in,
                              void* d_out, int out_size)
{
    const float* inputs = (const float*)d_in[0];
    const float* W_ih   = (const float*)d_in[1];
    const float* W_hh   = (const float*)d_in[2];
    const float* b_ih   = (const float*)d_in[3];
    const float* b_hh   = (const float*)d_in[4];
    const float* W_fc   = (const float*)d_in[5];
    const float* b_fc   = (const float*)d_in[6];
    float* out = (float*)d_out;

    const int smem1 = (256 * WPAD + 2 * BB * DD) * (int)sizeof(float);  // ~194 KB
    static int configured = 0;
    if (!configured) {
        cudaFuncSetAttribute(xproj_kernel,
                             cudaFuncAttributeMaxDynamicSharedMemorySize, smem1);
        configured = 1;
    }

    xproj_kernel<<<TT / 2, 256, smem1>>>(inputs, W_ih, b_ih, b_hh);
    rnn_kernel<<<2 * BB, 768>>>(W_hh, W_fc, b_fc, out);
}